// round 1
// baseline (speedup 1.0000x reference)
#include <cuda_runtime.h>
#include <cstdint>

// Problem constants (fixed by the reference)
#define BB 16
#define NN 8192
#define MM 2048
#define KK 32
#define CC 128

// out layout: [pts (B*M*K*3 floats)] ++ [features (B*M*K*C floats)]
// One CTA per (b, m). 256 threads = 8 warps.
//  - warp 0: computes normalized relative coords for all K=32 neighbors (lane = k)
//  - all warps: copy feature rows; warp w handles k = w, w+8, w+16, w+24;
//    each row is 128 floats = 32 float4 -> one float4 per lane, fully coalesced.
__global__ __launch_bounds__(256, 8)
void knn_gather_norm_kernel(const float* __restrict__ input,      // [B,N,C]
                            const float* __restrict__ points,     // [B,N,3]
                            const float* __restrict__ next_pts,   // [B,M,3]
                            const int*   __restrict__ indices,    // [B,M,K]
                            float* __restrict__ out_pts,          // [B,M,K,3]
                            float* __restrict__ out_feat)         // [B,M,K,C]
{
    const int bm = blockIdx.x;            // 0 .. B*M-1
    const int b  = bm / MM;

    __shared__ int sidx[KK];

    const int tid  = threadIdx.x;
    const int wid  = tid >> 5;
    const int lane = tid & 31;

    if (tid < KK) {
        sidx[tid] = indices[(size_t)bm * KK + tid];
    }
    __syncthreads();

    // ---- pts: warp 0, lane = neighbor k ----
    if (wid == 0) {
        const int k   = lane;
        const int idx = sidx[k];

        const float nx = __ldg(&next_pts[(size_t)bm * 3 + 0]);
        const float ny = __ldg(&next_pts[(size_t)bm * 3 + 1]);
        const float nz = __ldg(&next_pts[(size_t)bm * 3 + 2]);

        const float* p = points + ((size_t)b * NN + (size_t)idx) * 3;
        const float dx = __ldg(&p[0]) - nx;
        const float dy = __ldg(&p[1]) - ny;
        const float dz = __ldg(&p[2]) - nz;

        float mx = dx * dx + dy * dy + dz * dz;
        #pragma unroll
        for (int o = 16; o > 0; o >>= 1)
            mx = fmaxf(mx, __shfl_xor_sync(0xffffffffu, mx, o));

        float maxi = sqrtf(mx);
        if (maxi == 0.0f) maxi = 1.0f;
        const float inv = 1.0f / maxi;

        float* o = out_pts + ((size_t)bm * KK + (size_t)k) * 3;
        o[0] = dx * inv;
        o[1] = dy * inv;
        o[2] = dz * inv;
    }

    // ---- features: all 8 warps, one 512B row per warp-iteration ----
    #pragma unroll
    for (int k = wid; k < KK; k += 8) {
        const int idx = sidx[k];
        const float4* __restrict__ src =
            reinterpret_cast<const float4*>(input + ((size_t)b * NN + (size_t)idx) * CC);
        float4* __restrict__ dst =
            reinterpret_cast<float4*>(out_feat + ((size_t)bm * KK + (size_t)k) * CC);
        dst[lane] = src[lane];
    }
}

extern "C" void kernel_launch(void* const* d_in, const int* in_sizes, int n_in,
                              void* d_out, int out_size)
{
    const float* input    = (const float*)d_in[0];  // [B,N,C]
    const float* points   = (const float*)d_in[1];  // [B,N,3]
    const float* next_pts = (const float*)d_in[2];  // [B,M,3]
    const int*   indices  = (const int*)  d_in[3];  // [B,M,K]

    float* out_pts  = (float*)d_out;                         // B*M*K*3
    float* out_feat = out_pts + (size_t)BB * MM * KK * 3;    // B*M*K*C

    const int grid = BB * MM;   // 32768 CTAs
    knn_gather_norm_kernel<<<grid, 256>>>(input, points, next_pts, indices,
                                          out_pts, out_feat);
}